// round 15
// baseline (speedup 1.0000x reference)
#include <cuda_runtime.h>
#include <cuda_fp16.h>
#include <math.h>

#define N_NODES 8192
#define F_IN    512
#define HID     128
#define NCLS    16
#define CAP     160
#define KSPLIT  4

// ---------------- static scratch (no allocations allowed) ----------------
__device__ float  g_dinv [N_NODES];                       // d^{-1/2}
__device__ float  g_wself[N_NODES];                       // 1 + a_ii  (1 or 2)
__device__ int    g_cnt  [N_NODES];                       // neighbor count (self excluded)
__device__ unsigned g_colp[(size_t)N_NODES * CAP];        // plain neighbor columns
__device__ float  g_part[(size_t)KSPLIT * N_NODES * HID]; // split-K partials
__device__ float  g_h1  [(size_t)N_NODES * HID];          // fp32 residual h (raw)
__device__ __half g_fa  [(size_t)N_NODES * HID];          // fp16 s ping
__device__ __half g_fb  [(size_t)N_NODES * HID];          // fp16 s pong
__device__ float  g_relu[(size_t)N_NODES * HID];          // layer-1 output fp32
__device__ float  g_h2  [(size_t)N_NODES * NCLS];         // fp32 residual h2 (raw)
__device__ __half g_ca  [(size_t)N_NODES * NCLS];         // fp16 s ping (layer2)
__device__ __half g_cb  [(size_t)N_NODES * NCLS];         // fp16 s pong (layer2)

__device__ __constant__ float C_RES  = (float)(1.0 / 1.8);   // 1/(1+alpha)
__device__ __constant__ float C_PROP = (float)(0.8 / 1.8);   // alpha/(1+alpha)

// ---------------- 1: single-pass build: cols (self excluded) + dinv + wself ----------
__global__ void build_kernel(const float* __restrict__ adj) {
    int warp = (blockIdx.x * blockDim.x + threadIdx.x) >> 5;
    int lane = threadIdx.x & 31;
    if (warp >= N_NODES) return;
    const int row = warp;
    const float4* rowp = (const float4*)(adj + (size_t)row * N_NODES);
    size_t base = (size_t)row * CAP;
    int cnt = 0;
    float s = 0.f;

    float4 v = __ldg(&rowp[lane]);
    for (int j0 = 0; j0 < N_NODES; j0 += 128) {
        float4 nv;
        if (j0 + 128 < N_NODES) nv = __ldg(&rowp[(j0 + 128) / 4 + lane]);
        int j = j0 + lane * 4;
        v.x += (j + 0 == row) ? 1.f : 0.f;
        v.y += (j + 1 == row) ? 1.f : 0.f;
        v.z += (j + 2 == row) ? 1.f : 0.f;
        v.w += (j + 3 == row) ? 1.f : 0.f;
        s += v.x + v.y + v.z + v.w;       // degree includes self-loop weight
        float vv[4] = {v.x, v.y, v.z, v.w};
        int c = 0;
        bool em[4];
#pragma unroll
        for (int q = 0; q < 4; q++) {
            bool is_self = (j + q == row);
            if (is_self) g_wself[row] = vv[q];          // 1 + a_ii
            em[q] = (vv[q] != 0.f) && !is_self;
            c += em[q] ? 1 : 0;
        }
        int incl = c;
#pragma unroll
        for (int d = 1; d < 32; d <<= 1) {
            int t = __shfl_up_sync(0xffffffffu, incl, d);
            if (lane >= d) incl += t;
        }
        int total = __shfl_sync(0xffffffffu, incl, 31);
        int w = cnt + incl - c;
#pragma unroll
        for (int q = 0; q < 4; q++) {
            if (em[q]) {
                if (w < CAP) g_colp[base + w] = (unsigned)(j + q);
                w++;
            }
        }
        cnt += total;
        v = nv;
    }
#pragma unroll
    for (int d = 16; d; d >>= 1) s += __shfl_xor_sync(0xffffffffu, s, d);
    if (lane == 0) {
        g_cnt[row]  = (cnt < CAP) ? cnt : CAP;
        g_dinv[row] = rsqrtf(fmaxf(s, 1e-12f));          // d^{-1/2}
    }
}

// ---------------- 2: split-K SGEMM, 8x4 thread tile (BM=128, BN=64, BK=16) ----------
__global__ void __launch_bounds__(256) gemm1_kernel(const float* __restrict__ A,
                                                    const float* __restrict__ B) {
    const int BM = 128, BN = 64, BK = 16, KC = F_IN / KSPLIT;  // KC = 128
    __shared__ float As[BK][BM];
    __shared__ float Bs[BK][BN];
    const int m0 = blockIdx.x * BM;
    const int n0 = blockIdx.y * BN;
    const int kz = blockIdx.z;
    float* P = g_part + (size_t)kz * N_NODES * HID;
    const int t  = threadIdx.x;
    const int tx = t & 15;
    const int ty = t >> 4;
    const int ar = t >> 1;
    const int ac = (t & 1) * 8;
    const int bk = t >> 4;
    const int bc = (t & 15) * 4;

    float acc[8][4] = {};
    for (int k0 = kz * KC; k0 < kz * KC + KC; k0 += BK) {
        {
            const float* ap = A + (size_t)(m0 + ar) * F_IN + k0 + ac;
            float4 a0 = *(const float4*)(ap);
            float4 a1 = *(const float4*)(ap + 4);
            As[ac + 0][ar] = a0.x; As[ac + 1][ar] = a0.y;
            As[ac + 2][ar] = a0.z; As[ac + 3][ar] = a0.w;
            As[ac + 4][ar] = a1.x; As[ac + 5][ar] = a1.y;
            As[ac + 6][ar] = a1.z; As[ac + 7][ar] = a1.w;
        }
        {
            float4 b = *(const float4*)(B + (size_t)(k0 + bk) * HID + n0 + bc);
            Bs[bk][bc + 0] = b.x; Bs[bk][bc + 1] = b.y;
            Bs[bk][bc + 2] = b.z; Bs[bk][bc + 3] = b.w;
        }
        __syncthreads();
#pragma unroll
        for (int k = 0; k < BK; k++) {
            float av[8], bv[4];
#pragma unroll
            for (int i = 0; i < 8; i++) av[i] = As[k][ty * 8 + i];
#pragma unroll
            for (int j = 0; j < 4; j++) bv[j] = Bs[k][tx * 4 + j];
#pragma unroll
            for (int i = 0; i < 8; i++)
#pragma unroll
                for (int j = 0; j < 4; j++)
                    acc[i][j] = fmaf(av[i], bv[j], acc[i][j]);
        }
        __syncthreads();
    }
#pragma unroll
    for (int i = 0; i < 8; i++) {
        size_t off = (size_t)(m0 + ty * 8 + i) * HID + n0 + tx * 4;
        *(float4*)(P + off) = make_float4(acc[i][0], acc[i][1], acc[i][2], acc[i][3]);
    }
}

// ---------------- 2b: reduce split-K -> h1 (raw fp32) + fa (fp16, d^{-1/2}-scaled) ---
__global__ void reduce_kernel() {
    const size_t TOT = (size_t)N_NODES * HID / 4;        // 262144 float4
    size_t i0 = (size_t)blockIdx.x * 512 + threadIdx.x;
    size_t i1 = i0 + 256;
    const float4* p0 = (const float4*)g_part;
#pragma unroll
    for (int g = 0; g < 2; g++) {
        size_t i = g ? i1 : i0;
        if (i >= TOT) continue;
        float4 a = p0[i];
        float4 b = p0[TOT + i];
        float4 c = p0[2 * TOT + i];
        float4 d = p0[3 * TOT + i];
        float4 r;
        r.x = (a.x + b.x) + (c.x + d.x);
        r.y = (a.y + b.y) + (c.y + d.y);
        r.z = (a.z + b.z) + (c.z + d.z);
        r.w = (a.w + b.w) + (c.w + d.w);
        ((float4*)g_h1)[i] = r;
        float dsq = g_dinv[i >> 5];                      // row = i / 32
        __half2 h0 = __floats2half2_rn(r.x * dsq, r.y * dsq);
        __half2 h1 = __floats2half2_rn(r.z * dsq, r.w * dsq);
        ((uint2*)g_fa)[i] = make_uint2(*(unsigned*)&h0, *(unsigned*)&h1);
    }
}

// ---------------- 3: SpMM step, F=128: smem byte-offsets, 8-deep MLP, HADD2 ----------
template <bool FINAL>
__global__ void __launch_bounds__(256) spmm_h16(
        const __half* __restrict__ in, const float* __restrict__ h,
        __half* __restrict__ out, float* __restrict__ outf,
        const float* __restrict__ bias) {
    __shared__ unsigned scol[4 * CAP];                  // byte offsets (col*256)
    __shared__ float4 partial[4][32];
    const int warp = threadIdx.x >> 5;                  // 0..7
    const int lane = threadIdx.x & 31;
    const int rib  = warp >> 1;                         // row-in-block 0..3
    const int half = warp & 1;                          // edge half 0/1
    const int row0 = blockIdx.x * 4;
    const int row  = row0 + rib;

    // stage all 4 rows' columns as BYTE offsets into the fp16 feature matrix
    for (int i = threadIdx.x; i < 4 * CAP; i += 256)
        scol[i] = g_colp[(size_t)row0 * CAP + i] << 8;   // col * 256 bytes/row
    __syncthreads();

    const int cnt = g_cnt[row];
    const unsigned* sc = scol + rib * CAP;
    const char* pin = (const char*)in + (size_t)lane * 8;   // lane base

    // 8 rotating half2 accumulator sets -> 8 gathers in flight
    __half2 ax[8], ay[8];
#pragma unroll
    for (int s = 0; s < 8; s++) { ax[s] = __float2half2_rn(0.f); ay[s] = ax[s]; }
    int e = half;
    for (; e + 14 < cnt; e += 16) {
        uint2 o[8];
#pragma unroll
        for (int s = 0; s < 8; s++)
            o[s] = __ldg((const uint2*)(pin + sc[e + 2 * s]));
#pragma unroll
        for (int s = 0; s < 8; s++) {
            ax[s] = __hadd2(ax[s], *(__half2*)&o[s].x);
            ay[s] = __hadd2(ay[s], *(__half2*)&o[s].y);
        }
    }
    for (; e < cnt; e += 2) {
        uint2 o0 = __ldg((const uint2*)(pin + sc[e]));
        ax[0] = __hadd2(ax[0], *(__half2*)&o0.x);
        ay[0] = __hadd2(ay[0], *(__half2*)&o0.y);
    }
    float ax_f = 0.f, ay_f = 0.f, az_f = 0.f, aw_f = 0.f;
#pragma unroll
    for (int s = 0; s < 8; s++) {
        float2 fx = __half22float2(ax[s]);
        float2 fy = __half22float2(ay[s]);
        ax_f += fx.x; ay_f += fx.y; az_f += fy.x; aw_f += fy.y;
    }

    if (half == 0) partial[rib][lane] = make_float4(ax_f, ay_f, az_f, aw_f);
    __syncthreads();
    if (half == 1) {
        float4 p = partial[rib][lane];
        ax_f += p.x; ay_f += p.y; az_f += p.z; aw_f += p.w;
        // self contribution (fp32)
        {
            const float ws = g_wself[row];
            uint2 so = __ldg((const uint2*)(pin + ((size_t)row << 8)));
            float2 s0 = __half22float2(*(__half2*)&so.x);
            float2 s1 = __half22float2(*(__half2*)&so.y);
            ax_f = fmaf(ws, s0.x, ax_f);
            ay_f = fmaf(ws, s0.y, ay_f);
            az_f = fmaf(ws, s1.x, az_f);
            aw_f = fmaf(ws, s1.y, aw_f);
        }
        const float dsq = g_dinv[row];
        const float ca = FINAL ? (C_PROP * dsq) : (C_PROP * dsq * dsq);
        const float cb = FINAL ? C_RES : (C_RES * dsq);
        float4 hh = ((const float4*)h)[(size_t)row * 32 + lane];
        float4 r;
        r.x = ca * ax_f + cb * hh.x;
        r.y = ca * ay_f + cb * hh.y;
        r.z = ca * az_f + cb * hh.z;
        r.w = ca * aw_f + cb * hh.w;
        if (FINAL) {
            float4 b = ((const float4*)bias)[lane];
            r.x = fmaxf(r.x + b.x, 0.f);
            r.y = fmaxf(r.y + b.y, 0.f);
            r.z = fmaxf(r.z + b.z, 0.f);
            r.w = fmaxf(r.w + b.w, 0.f);
            ((float4*)outf)[(size_t)row * 32 + lane] = r;
        } else {
            __half2 h0 = __floats2half2_rn(r.x, r.y);
            __half2 h1 = __floats2half2_rn(r.z, r.w);
            ((uint2*)out)[(size_t)row * 32 + lane] =
                make_uint2(*(unsigned*)&h0, *(unsigned*)&h1);
        }
    }
}

// ---------------- 4: small GEMM  h2 = H @ W2 (raw fp32 + d^{-1/2}-scaled fp16) -------
__global__ void gemm2_kernel(const float* __restrict__ Hm, const float* __restrict__ W2) {
    __shared__ float sW[128 * 16];
    __shared__ float sH[16 * 128];
    int t = threadIdx.x;
    int row0 = blockIdx.x * 16;
    for (int i = t; i < 128 * 16; i += 256) sW[i] = W2[i];
    for (int i = t; i < 16 * 128; i += 256) {
        int r = i >> 7, k = i & 127;
        sH[i] = Hm[(size_t)(row0 + r) * 128 + k];
    }
    __syncthreads();
    int r = t >> 4, c = t & 15;
    float acc = 0.f;
#pragma unroll 8
    for (int k = 0; k < 128; k++) acc = fmaf(sH[r * 128 + k], sW[k * 16 + c], acc);
    size_t off = (size_t)(row0 + r) * 16 + c;
    g_h2[off] = acc;
    g_ca[off] = __float2half_rn(acc * g_dinv[row0 + r]);
}

// ---------------- 5: SpMM step, F=16: smem byte-offsets, 8-deep MLP, HADD2 -----------
template <bool FINAL>
__global__ void __launch_bounds__(256) spmm_c16(
        const __half* __restrict__ in, const float* __restrict__ h,
        __half* __restrict__ out, float* __restrict__ outf,
        const float* __restrict__ bias) {
    __shared__ unsigned scol[16 * CAP];                 // byte offsets (col*32)
    const int t   = threadIdx.x;
    const int rib = t >> 4;               // row-in-block 0..15
    const int l16 = t & 15;
    const int l8  = l16 & 7;              // half2 lane
    const int eg  = l16 >> 3;             // edge group 0/1
    const int row0 = blockIdx.x * 16;
    const int row  = row0 + rib;

    for (int i = t; i < 16 * CAP; i += 256)
        scol[i] = g_colp[(size_t)row0 * CAP + i] << 5;   // col * 32 bytes/row
    __syncthreads();

    const int cnt = g_cnt[row];
    const unsigned* sc = scol + rib * CAP;
    const char* pin = (const char*)in + (size_t)l8 * 4;
    __half2 acc[8];
#pragma unroll
    for (int s = 0; s < 8; s++) acc[s] = __float2half2_rn(0.f);
    int e = eg;
    for (; e + 14 < cnt; e += 16) {
        unsigned o[8];
#pragma unroll
        for (int s = 0; s < 8; s++)
            o[s] = __ldg((const unsigned*)(pin + sc[e + 2 * s]));
#pragma unroll
        for (int s = 0; s < 8; s++)
            acc[s] = __hadd2(acc[s], *(__half2*)&o[s]);
    }
    for (; e < cnt; e += 2) {
        unsigned o0 = __ldg((const unsigned*)(pin + sc[e]));
        acc[0] = __hadd2(acc[0], *(__half2*)&o0);
    }
    float a0 = 0.f, a1 = 0.f;
#pragma unroll
    for (int s = 0; s < 8; s++) {
        float2 f = __half22float2(acc[s]);
        a0 += f.x; a1 += f.y;
    }
    a0 += __shfl_xor_sync(0xffffffffu, a0, 8, 16);
    a1 += __shfl_xor_sync(0xffffffffu, a1, 8, 16);
    // self contribution
    {
        const float ws = g_wself[row];
        unsigned so = __ldg((const unsigned*)(pin + ((size_t)row << 5)));
        float2 sf = __half22float2(*(__half2*)&so);
        a0 = fmaf(ws, sf.x, a0);
        a1 = fmaf(ws, sf.y, a1);
    }
    const float dsq = g_dinv[row];
    const float ca = FINAL ? (C_PROP * dsq) : (C_PROP * dsq * dsq);
    const float cb = FINAL ? C_RES : (C_RES * dsq);
    float2 hh = ((const float2*)h)[(size_t)row * 8 + l8];
    float r0 = ca * a0 + cb * hh.x;
    float r1 = ca * a1 + cb * hh.y;
    if (FINAL) {
        float2 b = ((const float2*)bias)[l8];
        r0 += b.x;
        r1 += b.y;
        float m = fmaxf(r0, r1);
#pragma unroll
        for (int s = 1; s < 8; s <<= 1)
            m = fmaxf(m, __shfl_xor_sync(0xffffffffu, m, s, 8));
        float ssum = expf(r0 - m) + expf(r1 - m);
#pragma unroll
        for (int s = 1; s < 8; s <<= 1)
            ssum += __shfl_xor_sync(0xffffffffu, ssum, s, 8);
        float lse = m + logf(ssum);
        if (eg == 0)
            ((float2*)outf)[(size_t)row * 8 + l8] = make_float2(r0 - lse, r1 - lse);
    } else {
        if (eg == 0) {
            __half2 hv = __floats2half2_rn(r0, r1);
            ((unsigned*)out)[(size_t)row * 8 + l8] = *(unsigned*)&hv;
        }
    }
}

// ---------------- launch ----------------
extern "C" void kernel_launch(void* const* d_in, const int* in_sizes, int n_in,
                              void* d_out, int out_size) {
    const float* x   = (const float*)d_in[0];
    const float* adj = (const float*)d_in[1];
    const float* W1  = (const float*)d_in[2];
    const float* b1  = (const float*)d_in[3];
    const float* W2  = (const float*)d_in[4];
    const float* b2  = (const float*)d_in[5];
    float* out = (float*)d_out;

    void *ph1, *pfa, *pfb, *prl, *ph2, *pca, *pcb;
    cudaGetSymbolAddress(&ph1, g_h1);
    cudaGetSymbolAddress(&pfa, g_fa);
    cudaGetSymbolAddress(&pfb, g_fb);
    cudaGetSymbolAddress(&prl, g_relu);
    cudaGetSymbolAddress(&ph2, g_h2);
    cudaGetSymbolAddress(&pca, g_ca);
    cudaGetSymbolAddress(&pcb, g_cb);
    float*  h1 = (float*)ph1;
    __half* fa = (__half*)pfa;
    __half* fb = (__half*)pfb;
    float*  rl = (float*)prl;
    float*  h2 = (float*)ph2;
    __half* ca = (__half*)pca;
    __half* cb = (__half*)pcb;

    cudaStream_t sB;
    cudaStreamCreateWithFlags(&sB, cudaStreamNonBlocking);
    cudaEvent_t eFork, eJoin;
    cudaEventCreateWithFlags(&eFork, cudaEventDisableTiming);
    cudaEventCreateWithFlags(&eJoin, cudaEventDisableTiming);

    cudaEventRecord(eFork, 0);
    cudaStreamWaitEvent(sB, eFork, 0);

    // branch B: layer-1 dense transform (independent of adjacency)
    gemm1_kernel<<<dim3(N_NODES / 128, HID / 64, KSPLIT), 256, 0, sB>>>(x, W1);
    cudaEventRecord(eJoin, sB);

    // branch A (main stream): adjacency build
    build_kernel<<<N_NODES / 8, 256>>>(adj);

    cudaStreamWaitEvent(0, eJoin, 0);

    // reduce needs both g_part (branch B) and g_dinv (branch A)
    reduce_kernel<<<N_NODES * HID / 4 / 512, 256>>>();

    // layer 1: 8 diffusion steps in s-space; final unscales + bias + relu
    spmm_h16<false><<<N_NODES / 4, 256>>>(fa, h1, fb, nullptr, b1);
    spmm_h16<false><<<N_NODES / 4, 256>>>(fb, h1, fa, nullptr, b1);
    spmm_h16<false><<<N_NODES / 4, 256>>>(fa, h1, fb, nullptr, b1);
    spmm_h16<false><<<N_NODES / 4, 256>>>(fb, h1, fa, nullptr, b1);
    spmm_h16<false><<<N_NODES / 4, 256>>>(fa, h1, fb, nullptr, b1);
    spmm_h16<false><<<N_NODES / 4, 256>>>(fb, h1, fa, nullptr, b1);
    spmm_h16<false><<<N_NODES / 4, 256>>>(fa, h1, fb, nullptr, b1);
    spmm_h16<true ><<<N_NODES / 4, 256>>>(fb, h1, nullptr, rl, b1);

    // layer 2: h2 = relu_out @ W2; 8 s-space steps; final unscale+bias+log_softmax
    gemm2_kernel<<<N_NODES / 16, 256>>>(rl, W2);
    spmm_c16<false><<<N_NODES / 16, 256>>>(ca, h2, cb, nullptr, b2);
    spmm_c16<false><<<N_NODES / 16, 256>>>(cb, h2, ca, nullptr, b2);
    spmm_c16<false><<<N_NODES / 16, 256>>>(ca, h2, cb, nullptr, b2);
    spmm_c16<false><<<N_NODES / 16, 256>>>(cb, h2, ca, nullptr, b2);
    spmm_c16<false><<<N_NODES / 16, 256>>>(ca, h2, cb, nullptr, b2);
    spmm_c16<false><<<N_NODES / 16, 256>>>(cb, h2, ca, nullptr, b2);
    spmm_c16<false><<<N_NODES / 16, 256>>>(ca, h2, cb, nullptr, b2);
    spmm_c16<true ><<<N_NODES / 16, 256>>>(cb, h2, nullptr, out, b2);

    cudaEventDestroy(eFork);
    cudaEventDestroy(eJoin);
    cudaStreamDestroy(sB);
}

// round 16
// speedup vs baseline: 1.0685x; 1.0685x over previous
#include <cuda_runtime.h>
#include <cuda_fp16.h>
#include <math.h>

#define N_NODES 8192
#define F_IN    512
#define HID     128
#define NCLS    16
#define CAP     160
#define KSPLIT  4

// ---------------- static scratch (no allocations allowed) ----------------
__device__ float  g_dinv [N_NODES];                       // d^{-1/2}
__device__ float  g_wself[N_NODES];                       // 1 + a_ii  (1 or 2)
__device__ int    g_cnt  [N_NODES];                       // neighbor count (self excluded)
__device__ unsigned g_colp[(size_t)N_NODES * CAP];        // plain neighbor columns
__device__ float  g_part[(size_t)KSPLIT * N_NODES * HID]; // split-K partials
__device__ float  g_h1  [(size_t)N_NODES * HID];          // fp32 residual h (raw)
__device__ __half g_fa  [(size_t)N_NODES * HID];          // fp16 s ping
__device__ __half g_fb  [(size_t)N_NODES * HID];          // fp16 s pong
__device__ float  g_relu[(size_t)N_NODES * HID];          // layer-1 output fp32
__device__ float  g_h2  [(size_t)N_NODES * NCLS];         // fp32 residual h2 (raw)
__device__ __half g_ca  [(size_t)N_NODES * NCLS];         // fp16 s ping (layer2)
__device__ __half g_cb  [(size_t)N_NODES * NCLS];         // fp16 s pong (layer2)

__device__ __constant__ float C_RES  = (float)(1.0 / 1.8);   // 1/(1+alpha)
__device__ __constant__ float C_PROP = (float)(0.8 / 1.8);   // alpha/(1+alpha)

// ---------------- 1: single-pass build: cols (self excluded) + dinv + wself ----------
__global__ void build_kernel(const float* __restrict__ adj) {
    int warp = (blockIdx.x * blockDim.x + threadIdx.x) >> 5;
    int lane = threadIdx.x & 31;
    if (warp >= N_NODES) return;
    const int row = warp;
    const float4* rowp = (const float4*)(adj + (size_t)row * N_NODES);
    size_t base = (size_t)row * CAP;
    int cnt = 0;
    float s = 0.f;

    float4 v = __ldg(&rowp[lane]);
    for (int j0 = 0; j0 < N_NODES; j0 += 128) {
        float4 nv;
        if (j0 + 128 < N_NODES) nv = __ldg(&rowp[(j0 + 128) / 4 + lane]);
        int j = j0 + lane * 4;
        v.x += (j + 0 == row) ? 1.f : 0.f;
        v.y += (j + 1 == row) ? 1.f : 0.f;
        v.z += (j + 2 == row) ? 1.f : 0.f;
        v.w += (j + 3 == row) ? 1.f : 0.f;
        s += v.x + v.y + v.z + v.w;       // degree includes self-loop weight
        float vv[4] = {v.x, v.y, v.z, v.w};
        int c = 0;
        bool em[4];
#pragma unroll
        for (int q = 0; q < 4; q++) {
            bool is_self = (j + q == row);
            if (is_self) g_wself[row] = vv[q];          // 1 + a_ii
            em[q] = (vv[q] != 0.f) && !is_self;
            c += em[q] ? 1 : 0;
        }
        int incl = c;
#pragma unroll
        for (int d = 1; d < 32; d <<= 1) {
            int t = __shfl_up_sync(0xffffffffu, incl, d);
            if (lane >= d) incl += t;
        }
        int total = __shfl_sync(0xffffffffu, incl, 31);
        int w = cnt + incl - c;
#pragma unroll
        for (int q = 0; q < 4; q++) {
            if (em[q]) {
                if (w < CAP) g_colp[base + w] = (unsigned)(j + q);
                w++;
            }
        }
        cnt += total;
        v = nv;
    }
#pragma unroll
    for (int d = 16; d; d >>= 1) s += __shfl_xor_sync(0xffffffffu, s, d);
    if (lane == 0) {
        g_cnt[row]  = (cnt < CAP) ? cnt : CAP;
        g_dinv[row] = rsqrtf(fmaxf(s, 1e-12f));          // d^{-1/2}
    }
}

// ---------------- 2: split-K SGEMM, 8x4 thread tile (BM=128, BN=64, BK=16) ----------
__global__ void __launch_bounds__(256) gemm1_kernel(const float* __restrict__ A,
                                                    const float* __restrict__ B) {
    const int BM = 128, BN = 64, BK = 16, KC = F_IN / KSPLIT;  // KC = 128
    __shared__ float As[BK][BM];
    __shared__ float Bs[BK][BN];
    const int m0 = blockIdx.x * BM;
    const int n0 = blockIdx.y * BN;
    const int kz = blockIdx.z;
    float* P = g_part + (size_t)kz * N_NODES * HID;
    const int t  = threadIdx.x;
    const int tx = t & 15;
    const int ty = t >> 4;
    const int ar = t >> 1;
    const int ac = (t & 1) * 8;
    const int bk = t >> 4;
    const int bc = (t & 15) * 4;

    float acc[8][4] = {};
    for (int k0 = kz * KC; k0 < kz * KC + KC; k0 += BK) {
        {
            const float* ap = A + (size_t)(m0 + ar) * F_IN + k0 + ac;
            float4 a0 = *(const float4*)(ap);
            float4 a1 = *(const float4*)(ap + 4);
            As[ac + 0][ar] = a0.x; As[ac + 1][ar] = a0.y;
            As[ac + 2][ar] = a0.z; As[ac + 3][ar] = a0.w;
            As[ac + 4][ar] = a1.x; As[ac + 5][ar] = a1.y;
            As[ac + 6][ar] = a1.z; As[ac + 7][ar] = a1.w;
        }
        {
            float4 b = *(const float4*)(B + (size_t)(k0 + bk) * HID + n0 + bc);
            Bs[bk][bc + 0] = b.x; Bs[bk][bc + 1] = b.y;
            Bs[bk][bc + 2] = b.z; Bs[bk][bc + 3] = b.w;
        }
        __syncthreads();
#pragma unroll
        for (int k = 0; k < BK; k++) {
            float av[8], bv[4];
#pragma unroll
            for (int i = 0; i < 8; i++) av[i] = As[k][ty * 8 + i];
#pragma unroll
            for (int j = 0; j < 4; j++) bv[j] = Bs[k][tx * 4 + j];
#pragma unroll
            for (int i = 0; i < 8; i++)
#pragma unroll
                for (int j = 0; j < 4; j++)
                    acc[i][j] = fmaf(av[i], bv[j], acc[i][j]);
        }
        __syncthreads();
    }
#pragma unroll
    for (int i = 0; i < 8; i++) {
        size_t off = (size_t)(m0 + ty * 8 + i) * HID + n0 + tx * 4;
        *(float4*)(P + off) = make_float4(acc[i][0], acc[i][1], acc[i][2], acc[i][3]);
    }
}

// ---------------- 2b: reduce split-K -> h1 (raw fp32) + fa (fp16, d^{-1/2}-scaled) ---
__global__ void reduce_kernel() {
    const size_t TOT = (size_t)N_NODES * HID / 4;        // 262144 float4
    size_t i0 = (size_t)blockIdx.x * 512 + threadIdx.x;
    size_t i1 = i0 + 256;
    const float4* p0 = (const float4*)g_part;
#pragma unroll
    for (int g = 0; g < 2; g++) {
        size_t i = g ? i1 : i0;
        if (i >= TOT) continue;
        float4 a = p0[i];
        float4 b = p0[TOT + i];
        float4 c = p0[2 * TOT + i];
        float4 d = p0[3 * TOT + i];
        float4 r;
        r.x = (a.x + b.x) + (c.x + d.x);
        r.y = (a.y + b.y) + (c.y + d.y);
        r.z = (a.z + b.z) + (c.z + d.z);
        r.w = (a.w + b.w) + (c.w + d.w);
        ((float4*)g_h1)[i] = r;
        float dsq = g_dinv[i >> 5];                      // row = i / 32
        __half2 h0 = __floats2half2_rn(r.x * dsq, r.y * dsq);
        __half2 h1 = __floats2half2_rn(r.z * dsq, r.w * dsq);
        ((uint2*)g_fa)[i] = make_uint2(*(unsigned*)&h0, *(unsigned*)&h1);
    }
}

// ---------------- 3: SpMM step, F=128: smem byte-offsets, 4-deep MLP, HADD2 ----------
template <bool FINAL>
__global__ void __launch_bounds__(256, 8) spmm_h16(
        const __half* __restrict__ in, const float* __restrict__ h,
        __half* __restrict__ out, float* __restrict__ outf,
        const float* __restrict__ bias) {
    __shared__ unsigned scol[4 * CAP];                  // byte offsets (col*256)
    __shared__ float4 partial[4][32];
    const int warp = threadIdx.x >> 5;                  // 0..7
    const int lane = threadIdx.x & 31;
    const int rib  = warp >> 1;                         // row-in-block 0..3
    const int half = warp & 1;                          // edge half 0/1
    const int row0 = blockIdx.x * 4;
    const int row  = row0 + rib;

    // stage all 4 rows' columns as BYTE offsets into the fp16 feature matrix
    for (int i = threadIdx.x; i < 4 * CAP; i += 256)
        scol[i] = g_colp[(size_t)row0 * CAP + i] << 8;   // col * 256 bytes/row
    __syncthreads();

    const int cnt = g_cnt[row];
    const unsigned* sc = scol + rib * CAP;
    const char* pin = (const char*)in + (size_t)lane * 8;   // lane base

    // 4 rotating half2 accumulator sets -> 4 gathers in flight (regs <= 32)
    __half2 ax[4], ay[4];
#pragma unroll
    for (int s = 0; s < 4; s++) { ax[s] = __float2half2_rn(0.f); ay[s] = ax[s]; }
    int e = half;
    for (; e + 6 < cnt; e += 8) {
        uint2 o0 = __ldg((const uint2*)(pin + sc[e]));
        uint2 o1 = __ldg((const uint2*)(pin + sc[e + 2]));
        uint2 o2 = __ldg((const uint2*)(pin + sc[e + 4]));
        uint2 o3 = __ldg((const uint2*)(pin + sc[e + 6]));
        ax[0] = __hadd2(ax[0], *(__half2*)&o0.x); ay[0] = __hadd2(ay[0], *(__half2*)&o0.y);
        ax[1] = __hadd2(ax[1], *(__half2*)&o1.x); ay[1] = __hadd2(ay[1], *(__half2*)&o1.y);
        ax[2] = __hadd2(ax[2], *(__half2*)&o2.x); ay[2] = __hadd2(ay[2], *(__half2*)&o2.y);
        ax[3] = __hadd2(ax[3], *(__half2*)&o3.x); ay[3] = __hadd2(ay[3], *(__half2*)&o3.y);
    }
    for (; e < cnt; e += 2) {
        uint2 o0 = __ldg((const uint2*)(pin + sc[e]));
        ax[0] = __hadd2(ax[0], *(__half2*)&o0.x);
        ay[0] = __hadd2(ay[0], *(__half2*)&o0.y);
    }
    float ax_f = 0.f, ay_f = 0.f, az_f = 0.f, aw_f = 0.f;
#pragma unroll
    for (int s = 0; s < 4; s++) {
        float2 fx = __half22float2(ax[s]);
        float2 fy = __half22float2(ay[s]);
        ax_f += fx.x; ay_f += fx.y; az_f += fy.x; aw_f += fy.y;
    }

    if (half == 0) partial[rib][lane] = make_float4(ax_f, ay_f, az_f, aw_f);
    __syncthreads();
    if (half == 1) {
        float4 p = partial[rib][lane];
        ax_f += p.x; ay_f += p.y; az_f += p.z; aw_f += p.w;
        // self contribution (fp32)
        {
            const float ws = g_wself[row];
            uint2 so = __ldg((const uint2*)(pin + ((size_t)row << 8)));
            float2 s0 = __half22float2(*(__half2*)&so.x);
            float2 s1 = __half22float2(*(__half2*)&so.y);
            ax_f = fmaf(ws, s0.x, ax_f);
            ay_f = fmaf(ws, s0.y, ay_f);
            az_f = fmaf(ws, s1.x, az_f);
            aw_f = fmaf(ws, s1.y, aw_f);
        }
        const float dsq = g_dinv[row];
        const float ca = FINAL ? (C_PROP * dsq) : (C_PROP * dsq * dsq);
        const float cb = FINAL ? C_RES : (C_RES * dsq);
        float4 hh = ((const float4*)h)[(size_t)row * 32 + lane];
        float4 r;
        r.x = ca * ax_f + cb * hh.x;
        r.y = ca * ay_f + cb * hh.y;
        r.z = ca * az_f + cb * hh.z;
        r.w = ca * aw_f + cb * hh.w;
        if (FINAL) {
            float4 b = ((const float4*)bias)[lane];
            r.x = fmaxf(r.x + b.x, 0.f);
            r.y = fmaxf(r.y + b.y, 0.f);
            r.z = fmaxf(r.z + b.z, 0.f);
            r.w = fmaxf(r.w + b.w, 0.f);
            ((float4*)outf)[(size_t)row * 32 + lane] = r;
        } else {
            __half2 h0 = __floats2half2_rn(r.x, r.y);
            __half2 h1 = __floats2half2_rn(r.z, r.w);
            ((uint2*)out)[(size_t)row * 32 + lane] =
                make_uint2(*(unsigned*)&h0, *(unsigned*)&h1);
        }
    }
}

// ---------------- 4: small GEMM  h2 = H @ W2 (raw fp32 + d^{-1/2}-scaled fp16) -------
__global__ void gemm2_kernel(const float* __restrict__ Hm, const float* __restrict__ W2) {
    __shared__ float sW[128 * 16];
    __shared__ float sH[16 * 128];
    int t = threadIdx.x;
    int row0 = blockIdx.x * 16;
    for (int i = t; i < 128 * 16; i += 256) sW[i] = W2[i];
    for (int i = t; i < 16 * 128; i += 256) {
        int r = i >> 7, k = i & 127;
        sH[i] = Hm[(size_t)(row0 + r) * 128 + k];
    }
    __syncthreads();
    int r = t >> 4, c = t & 15;
    float acc = 0.f;
#pragma unroll 8
    for (int k = 0; k < 128; k++) acc = fmaf(sH[r * 128 + k], sW[k * 16 + c], acc);
    size_t off = (size_t)(row0 + r) * 16 + c;
    g_h2[off] = acc;
    g_ca[off] = __float2half_rn(acc * g_dinv[row0 + r]);
}

// ---------------- 5: SpMM step, F=16: smem byte-offsets, 4-deep MLP, HADD2 -----------
template <bool FINAL>
__global__ void __launch_bounds__(256, 8) spmm_c16(
        const __half* __restrict__ in, const float* __restrict__ h,
        __half* __restrict__ out, float* __restrict__ outf,
        const float* __restrict__ bias) {
    __shared__ unsigned scol[16 * CAP];                 // byte offsets (col*32)
    const int t   = threadIdx.x;
    const int rib = t >> 4;               // row-in-block 0..15
    const int l16 = t & 15;
    const int l8  = l16 & 7;              // half2 lane
    const int eg  = l16 >> 3;             // edge group 0/1
    const int row0 = blockIdx.x * 16;
    const int row  = row0 + rib;

    for (int i = t; i < 16 * CAP; i += 256)
        scol[i] = g_colp[(size_t)row0 * CAP + i] << 5;   // col * 32 bytes/row
    __syncthreads();

    const int cnt = g_cnt[row];
    const unsigned* sc = scol + rib * CAP;
    const char* pin = (const char*)in + (size_t)l8 * 4;
    __half2 acc[4];
#pragma unroll
    for (int s = 0; s < 4; s++) acc[s] = __float2half2_rn(0.f);
    int e = eg;
    for (; e + 6 < cnt; e += 8) {
        unsigned o0 = __ldg((const unsigned*)(pin + sc[e]));
        unsigned o1 = __ldg((const unsigned*)(pin + sc[e + 2]));
        unsigned o2 = __ldg((const unsigned*)(pin + sc[e + 4]));
        unsigned o3 = __ldg((const unsigned*)(pin + sc[e + 6]));
        acc[0] = __hadd2(acc[0], *(__half2*)&o0);
        acc[1] = __hadd2(acc[1], *(__half2*)&o1);
        acc[2] = __hadd2(acc[2], *(__half2*)&o2);
        acc[3] = __hadd2(acc[3], *(__half2*)&o3);
    }
    for (; e < cnt; e += 2) {
        unsigned o0 = __ldg((const unsigned*)(pin + sc[e]));
        acc[0] = __hadd2(acc[0], *(__half2*)&o0);
    }
    float a0 = 0.f, a1 = 0.f;
#pragma unroll
    for (int s = 0; s < 4; s++) {
        float2 f = __half22float2(acc[s]);
        a0 += f.x; a1 += f.y;
    }
    a0 += __shfl_xor_sync(0xffffffffu, a0, 8, 16);
    a1 += __shfl_xor_sync(0xffffffffu, a1, 8, 16);
    // self contribution
    {
        const float ws = g_wself[row];
        unsigned so = __ldg((const unsigned*)(pin + ((size_t)row << 5)));
        float2 sf = __half22float2(*(__half2*)&so);
        a0 = fmaf(ws, sf.x, a0);
        a1 = fmaf(ws, sf.y, a1);
    }
    const float dsq = g_dinv[row];
    const float ca = FINAL ? (C_PROP * dsq) : (C_PROP * dsq * dsq);
    const float cb = FINAL ? C_RES : (C_RES * dsq);
    float2 hh = ((const float2*)h)[(size_t)row * 8 + l8];
    float r0 = ca * a0 + cb * hh.x;
    float r1 = ca * a1 + cb * hh.y;
    if (FINAL) {
        float2 b = ((const float2*)bias)[l8];
        r0 += b.x;
        r1 += b.y;
        float m = fmaxf(r0, r1);
#pragma unroll
        for (int s = 1; s < 8; s <<= 1)
            m = fmaxf(m, __shfl_xor_sync(0xffffffffu, m, s, 8));
        float ssum = expf(r0 - m) + expf(r1 - m);
#pragma unroll
        for (int s = 1; s < 8; s <<= 1)
            ssum += __shfl_xor_sync(0xffffffffu, ssum, s, 8);
        float lse = m + logf(ssum);
        if (eg == 0)
            ((float2*)outf)[(size_t)row * 8 + l8] = make_float2(r0 - lse, r1 - lse);
    } else {
        if (eg == 0) {
            __half2 hv = __floats2half2_rn(r0, r1);
            ((unsigned*)out)[(size_t)row * 8 + l8] = *(unsigned*)&hv;
        }
    }
}

// ---------------- launch ----------------
extern "C" void kernel_launch(void* const* d_in, const int* in_sizes, int n_in,
                              void* d_out, int out_size) {
    const float* x   = (const float*)d_in[0];
    const float* adj = (const float*)d_in[1];
    const float* W1  = (const float*)d_in[2];
    const float* b1  = (const float*)d_in[3];
    const float* W2  = (const float*)d_in[4];
    const float* b2  = (const float*)d_in[5];
    float* out = (float*)d_out;

    void *ph1, *pfa, *pfb, *prl, *ph2, *pca, *pcb;
    cudaGetSymbolAddress(&ph1, g_h1);
    cudaGetSymbolAddress(&pfa, g_fa);
    cudaGetSymbolAddress(&pfb, g_fb);
    cudaGetSymbolAddress(&prl, g_relu);
    cudaGetSymbolAddress(&ph2, g_h2);
    cudaGetSymbolAddress(&pca, g_ca);
    cudaGetSymbolAddress(&pcb, g_cb);
    float*  h1 = (float*)ph1;
    __half* fa = (__half*)pfa;
    __half* fb = (__half*)pfb;
    float*  rl = (float*)prl;
    float*  h2 = (float*)ph2;
    __half* ca = (__half*)pca;
    __half* cb = (__half*)pcb;

    cudaStream_t sB;
    cudaStreamCreateWithFlags(&sB, cudaStreamNonBlocking);
    cudaEvent_t eFork, eJoin;
    cudaEventCreateWithFlags(&eFork, cudaEventDisableTiming);
    cudaEventCreateWithFlags(&eJoin, cudaEventDisableTiming);

    cudaEventRecord(eFork, 0);
    cudaStreamWaitEvent(sB, eFork, 0);

    // branch B: layer-1 dense transform (independent of adjacency)
    gemm1_kernel<<<dim3(N_NODES / 128, HID / 64, KSPLIT), 256, 0, sB>>>(x, W1);
    cudaEventRecord(eJoin, sB);

    // branch A (main stream): adjacency build
    build_kernel<<<N_NODES / 8, 256>>>(adj);

    cudaStreamWaitEvent(0, eJoin, 0);

    // reduce needs both g_part (branch B) and g_dinv (branch A)
    reduce_kernel<<<N_NODES * HID / 4 / 512, 256>>>();

    // layer 1: 8 diffusion steps in s-space; final unscales + bias + relu
    spmm_h16<false><<<N_NODES / 4, 256>>>(fa, h1, fb, nullptr, b1);
    spmm_h16<false><<<N_NODES / 4, 256>>>(fb, h1, fa, nullptr, b1);
    spmm_h16<false><<<N_NODES / 4, 256>>>(fa, h1, fb, nullptr, b1);
    spmm_h16<false><<<N_NODES / 4, 256>>>(fb, h1, fa, nullptr, b1);
    spmm_h16<false><<<N_NODES / 4, 256>>>(fa, h1, fb, nullptr, b1);
    spmm_h16<false><<<N_NODES / 4, 256>>>(fb, h1, fa, nullptr, b1);
    spmm_h16<false><<<N_NODES / 4, 256>>>(fa, h1, fb, nullptr, b1);
    spmm_h16<true ><<<N_NODES / 4, 256>>>(fb, h1, nullptr, rl, b1);

    // layer 2: h2 = relu_out @ W2; 8 s-space steps; final unscale+bias+log_softmax
    gemm2_kernel<<<N_NODES / 16, 256>>>(rl, W2);
    spmm_c16<false><<<N_NODES / 16, 256>>>(ca, h2, cb, nullptr, b2);
    spmm_c16<false><<<N_NODES / 16, 256>>>(cb, h2, ca, nullptr, b2);
    spmm_c16<false><<<N_NODES / 16, 256>>>(ca, h2, cb, nullptr, b2);
    spmm_c16<false><<<N_NODES / 16, 256>>>(cb, h2, ca, nullptr, b2);
    spmm_c16<false><<<N_NODES / 16, 256>>>(ca, h2, cb, nullptr, b2);
    spmm_c16<false><<<N_NODES / 16, 256>>>(cb, h2, ca, nullptr, b2);
    spmm_c16<false><<<N_NODES / 16, 256>>>(ca, h2, cb, nullptr, b2);
    spmm_c16<true ><<<N_NODES / 16, 256>>>(cb, h2, nullptr, out, b2);

    cudaEventDestroy(eFork);
    cudaEventDestroy(eJoin);
    cudaStreamDestroy(sB);
}